// round 2
// baseline (speedup 1.0000x reference)
#include <cuda_runtime.h>
#include <math.h>

// Problem constants
#define Tn 128
#define Bn 2048
#define Hn 256
#define In0 18

// Tiling
#define KC 16
#define NTHREADS 256
#define HS_LD 68    // smem stride for activation tile (16B-aligned friendly, bank spread)
#define WS_LD 196   // smem stride for weight tile (<=192 gate-cols + pad)

typedef unsigned long long u64;

// Ring buffers for hidden state (depth 2).
__device__ float g_h1[2][Bn * Hn];
__device__ float g_h2[2][Bn * Hn];

__device__ __forceinline__ float sigf(float x) { return 1.f / (1.f + expf(-x)); }

// packed 2-wide fp32 FMA (FFMA2) — only reachable via PTX
__device__ __forceinline__ void ffma2(u64& d, u64 a, u64 b) {
    asm("fma.rn.f32x2 %0, %1, %2, %0;" : "+l"(d) : "l"(a), "l"(b));
}
__device__ __forceinline__ u64 dup2(float x) {
    u64 r; asm("mov.b64 %0, {%1, %1};" : "=l"(r) : "f"(x)); return r;
}
__device__ __forceinline__ float2 unpack2(u64 v) {
    float2 f; asm("mov.b64 {%0, %1}, %2;" : "=f"(f.x), "=f"(f.y) : "l"(v)); return f;
}

// One accumulation stream over K:
//   acc{R,Z,a3}[ii][jp] (+)= A[b0+batch][k] * W[gate*Hn + j0+unit][k]
// BNT = units per tile (32 or 64), II = batch rows per thread (64/ (NTHREADS/(BNT/4)) ).
// Accumulators are f32x2 pairs along the unit dimension.
template<int BNT, int II>
__device__ __forceinline__ void stream_mm(
    const float* __restrict__ A, int lda, int K,
    const float* __restrict__ W, int ldw,
    int b0, int j0, int tid, bool vec,
    float (*hs)[HS_LD], float (*ws)[WS_LD],
    u64 (&aR)[II][2], u64 (&aZ)[II][2], u64 (&a3)[II][2])
{
    constexpr int WSLOTS = 3 * BNT * 4;                       // float4 slots per chunk
    constexpr int NWL = (WSLOTS + NTHREADS - 1) / NTHREADS;   // 3 (BNT=64) or 2 (BNT=32)
    const int tx = tid % (BNT / 4);
    const int ty = tid / (BNT / 4);
    const int arow = tid >> 2;    // 0..63 (batch row for staging)
    const int akv  = tid & 3;     // k-quad
    const int nch = (K + KC - 1) / KC;

    float fa[4];
    float fw[NWL][4];

    auto fetch = [&](int k0) {
        // activations
        if (vec) {
            const float4 t4 = *(const float4*)(A + (size_t)(b0 + arow) * lda + k0 + akv * 4);
            fa[0] = t4.x; fa[1] = t4.y; fa[2] = t4.z; fa[3] = t4.w;
        } else {
            #pragma unroll
            for (int i = 0; i < 4; ++i) {
                const int k = k0 + akv * 4 + i;
                fa[i] = (k < K) ? A[(size_t)(b0 + arow) * lda + k] : 0.f;
            }
        }
        // weights (rows 0..3*BNT-1 map gate-major: row = g*BNT + jr)
        #pragma unroll
        for (int s = 0; s < NWL; ++s) {
            const int slot = tid + s * NTHREADS;
            if (slot < WSLOTS) {
                const int row = slot >> 2, kv = slot & 3;
                const int g = row / BNT, jr = row % BNT;
                const float* wr = W + (size_t)(g * Hn + j0 + jr) * ldw;
                if (vec) {
                    const float4 w4 = *(const float4*)(wr + k0 + kv * 4);
                    fw[s][0] = w4.x; fw[s][1] = w4.y; fw[s][2] = w4.z; fw[s][3] = w4.w;
                } else {
                    #pragma unroll
                    for (int i = 0; i < 4; ++i) {
                        const int k = k0 + kv * 4 + i;
                        fw[s][i] = (k < K) ? wr[k] : 0.f;
                    }
                }
            }
        }
    };

    fetch(0);

    for (int c = 0; c < nch; ++c) {
        __syncthreads();   // previous user done with smem
        #pragma unroll
        for (int i = 0; i < 4; ++i) hs[akv * 4 + i][arow] = fa[i];
        #pragma unroll
        for (int s = 0; s < NWL; ++s) {
            const int slot = tid + s * NTHREADS;
            if (slot < WSLOTS) {
                const int row = slot >> 2, kv = slot & 3;
                #pragma unroll
                for (int i = 0; i < 4; ++i) ws[kv * 4 + i][row] = fw[s][i];
            }
        }
        __syncthreads();

        if (c + 1 < nch) fetch((c + 1) * KC);

        // FFMA2 core
        #pragma unroll
        for (int k = 0; k < KC; ++k) {
            u64 hd[II];
            if (II == 4) {
                const float4 hb = *(const float4*)&hs[k][ty * 4];
                hd[0] = dup2(hb.x); hd[1] = dup2(hb.y); hd[2] = dup2(hb.z); hd[3] = dup2(hb.w);
            } else {
                const float2 hb = *(const float2*)&hs[k][ty * 2];
                hd[0] = dup2(hb.x); hd[1] = dup2(hb.y);
            }
            const ulonglong2 wr = *(const ulonglong2*)&ws[k][0 * BNT + tx * 4];
            const ulonglong2 wz = *(const ulonglong2*)&ws[k][1 * BNT + tx * 4];
            const ulonglong2 wn = *(const ulonglong2*)&ws[k][2 * BNT + tx * 4];
            #pragma unroll
            for (int ii = 0; ii < II; ++ii) {
                ffma2(aR[ii][0], hd[ii], wr.x); ffma2(aR[ii][1], hd[ii], wr.y);
                ffma2(aZ[ii][0], hd[ii], wz.x); ffma2(aZ[ii][1], hd[ii], wz.y);
                ffma2(a3[ii][0], hd[ii], wn.x); ffma2(a3[ii][1], hd[ii], wn.y);
            }
        }
    }
}

template<int BNT, int II>
__device__ __forceinline__ void gru_epilogue(
    const float* __restrict__ bih, const float* __restrict__ bhh,
    const float* __restrict__ hprev, float* __restrict__ hout,
    int b0, int j0, int tid,
    u64 (&aR)[II][2], u64 (&aZ)[II][2], u64 (&aXN)[II][2], u64 (&aHN)[II][2])
{
    const int tx = tid % (BNT / 4);
    const int ty = tid / (BNT / 4);
    #pragma unroll
    for (int ii = 0; ii < II; ++ii) {
        const int b = b0 + ty * II + ii;
        #pragma unroll
        for (int jp = 0; jp < 2; ++jp) {
            const float2 r2  = unpack2(aR[ii][jp]);
            const float2 z2  = unpack2(aZ[ii][jp]);
            const float2 xn2 = unpack2(aXN[ii][jp]);
            const float2 hn2 = unpack2(aHN[ii][jp]);
            #pragma unroll
            for (int jh = 0; jh < 2; ++jh) {
                const int j = j0 + tx * 4 + jp * 2 + jh;
                const float br = bih[j] + bhh[j];
                const float bz = bih[Hn + j] + bhh[Hn + j];
                const float rv = jh ? r2.y : r2.x;
                const float zv = jh ? z2.y : z2.x;
                const float xnv = jh ? xn2.y : xn2.x;
                const float hnv = jh ? hn2.y : hn2.x;
                const float r = sigf(rv + br);
                const float z = sigf(zv + bz);
                const float n = tanhf(xnv + bih[2 * Hn + j] + r * (hnv + bhh[2 * Hn + j]));
                const float hp = hprev[(size_t)b * Hn + j];
                hout[(size_t)b * Hn + j] = (1.f - z) * n + z * hp;
            }
        }
    }
}

// Pipelined super-step l: CTAs [0,128) run layer0 at t=l (64x64 tiles),
// CTAs [128,384) run layer1 at t=l-1 (64x32 tiles) -> near-equal work per CTA.
__global__ void __launch_bounds__(NTHREADS, 2)
gru_step_kernel(const float* __restrict__ x,
                const float* __restrict__ Wih0, const float* __restrict__ Whh0,
                const float* __restrict__ bih0, const float* __restrict__ bhh0,
                const float* __restrict__ Wih1, const float* __restrict__ Whh1,
                const float* __restrict__ bih1, const float* __restrict__ bhh1,
                int l)
{
    __shared__ float hs[KC][HS_LD];
    __shared__ float ws[KC][WS_LD];

    const int cta = blockIdx.x;
    const bool L1 = (cta >= 128);
    const int t = L1 ? (l - 1) : l;
    if (t < 0 || t >= Tn) return;
    const int tid = threadIdx.x;

    if (!L1) {
        const int b0 = (cta >> 2) * 64;
        const int j0 = (cta & 3) * 64;
        u64 aR[4][2] = {}, aZ[4][2] = {}, aXN[4][2] = {}, aHN[4][2] = {};
        const float* xin   = x + (size_t)t * Bn * In0;
        const float* hprev = g_h1[(t + 1) & 1];
        float*       hout  = g_h1[t & 1];
        stream_mm<64, 4>(xin, In0, In0, Wih0, In0, b0, j0, tid, false, hs, ws, aR, aZ, aXN);
        stream_mm<64, 4>(hprev, Hn, Hn, Whh0, Hn, b0, j0, tid, true, hs, ws, aR, aZ, aHN);
        gru_epilogue<64, 4>(bih0, bhh0, hprev, hout, b0, j0, tid, aR, aZ, aXN, aHN);
    } else {
        const int idx = cta - 128;           // 0..255
        const int b0 = (idx >> 3) * 64;      // 32 batch tiles
        const int j0 = (idx & 7) * 32;       // 8 unit tiles
        u64 aR[2][2] = {}, aZ[2][2] = {}, aXN[2][2] = {}, aHN[2][2] = {};
        const float* xin   = g_h1[t & 1];    // h1[t], produced by previous launch
        const float* hprev = g_h2[(t + 1) & 1];
        float*       hout  = g_h2[t & 1];
        stream_mm<32, 2>(xin, Hn, Hn, Wih1, Hn, b0, j0, tid, true, hs, ws, aR, aZ, aXN);
        stream_mm<32, 2>(hprev, Hn, Hn, Whh1, Hn, b0, j0, tid, true, hs, ws, aR, aZ, aHN);
        gru_epilogue<32, 2>(bih1, bhh1, hprev, hout, b0, j0, tid, aR, aZ, aXN, aHN);
    }
}

// Final FC + sigmoid*2-1 on h2[T-1]. One warp per batch row.
__global__ void fc_kernel(const float* __restrict__ fcw, const float* __restrict__ fcb,
                          float* __restrict__ out)
{
    const int warp = (blockIdx.x * blockDim.x + threadIdx.x) >> 5;
    const int lane = threadIdx.x & 31;
    if (warp >= Bn) return;
    const float* h = g_h2[(Tn - 1) & 1] + (size_t)warp * Hn;
    float a0 = 0.f, a1 = 0.f, a2 = 0.f, a3 = 0.f;
    for (int k = lane; k < Hn; k += 32) {
        const float hv = h[k];
        a0 = fmaf(hv, fcw[k], a0);
        a1 = fmaf(hv, fcw[Hn + k], a1);
        a2 = fmaf(hv, fcw[2 * Hn + k], a2);
        a3 = fmaf(hv, fcw[3 * Hn + k], a3);
    }
    #pragma unroll
    for (int s = 16; s; s >>= 1) {
        a0 += __shfl_xor_sync(0xFFFFFFFFu, a0, s);
        a1 += __shfl_xor_sync(0xFFFFFFFFu, a1, s);
        a2 += __shfl_xor_sync(0xFFFFFFFFu, a2, s);
        a3 += __shfl_xor_sync(0xFFFFFFFFu, a3, s);
    }
    if (lane == 0) {
        out[warp * 4 + 0] = 2.f * sigf(a0 + fcb[0]) - 1.f;
        out[warp * 4 + 1] = 2.f * sigf(a1 + fcb[1]) - 1.f;
        out[warp * 4 + 2] = 2.f * sigf(a2 + fcb[2]) - 1.f;
        out[warp * 4 + 3] = 2.f * sigf(a3 + fcb[3]) - 1.f;
    }
}

extern "C" void kernel_launch(void* const* d_in, const int* in_sizes, int n_in,
                              void* d_out, int out_size)
{
    const float* x    = (const float*)d_in[0];
    const float* Wih0 = (const float*)d_in[1];
    const float* Whh0 = (const float*)d_in[2];
    const float* bih0 = (const float*)d_in[3];
    const float* bhh0 = (const float*)d_in[4];
    const float* Wih1 = (const float*)d_in[5];
    const float* Whh1 = (const float*)d_in[6];
    const float* bih1 = (const float*)d_in[7];
    const float* bhh1 = (const float*)d_in[8];
    const float* fcw  = (const float*)d_in[9];
    const float* fcb  = (const float*)d_in[10];
    float* out = (float*)d_out;
    (void)in_sizes; (void)n_in; (void)out_size;

    // zero the "previous state" slots used at t=0 (slot (0+1)&1 == 1)
    void *p1 = nullptr, *p2 = nullptr;
    cudaGetSymbolAddress(&p1, g_h1);
    cudaGetSymbolAddress(&p2, g_h2);
    cudaMemsetAsync((char*)p1 + sizeof(float) * (size_t)Bn * Hn, 0,
                    sizeof(float) * (size_t)Bn * Hn, 0);
    cudaMemsetAsync((char*)p2 + sizeof(float) * (size_t)Bn * Hn, 0,
                    sizeof(float) * (size_t)Bn * Hn, 0);

    for (int l = 0; l <= Tn; ++l) {
        gru_step_kernel<<<384, NTHREADS>>>(x, Wih0, Whh0, bih0, bhh0,
                                           Wih1, Whh1, bih1, bhh1, l);
    }

    fc_kernel<<<(Bn * 32) / 256, 256>>>(fcw, fcb, out);
}

// round 3
// speedup vs baseline: 1.5245x; 1.5245x over previous
#include <cuda_runtime.h>
#include <math.h>

// Problem constants
#define Tn 128
#define Bn 2048
#define Hn 256
#define In0 18

// Tiling
#define KC 16
#define NTHREADS 256
#define HS_LD 68    // smem stride for activation tile (16B-aligned friendly, bank spread)
#define WS_LD 196   // smem stride for weight tile (<=192 gate-cols + pad)

typedef unsigned long long u64;

// Ring buffers for hidden state (depth 2).
__device__ float g_h1[2][Bn * Hn];
__device__ float g_h2[2][Bn * Hn];

__device__ __forceinline__ float sigf(float x) { return 1.f / (1.f + expf(-x)); }

// packed 2-wide fp32 FMA (FFMA2) — only reachable via PTX
__device__ __forceinline__ void ffma2(u64& d, u64 a, u64 b) {
    asm("fma.rn.f32x2 %0, %1, %2, %0;" : "+l"(d) : "l"(a), "l"(b));
}
__device__ __forceinline__ u64 dup2(float x) {
    u64 r; asm("mov.b64 %0, {%1, %1};" : "=l"(r) : "f"(x)); return r;
}
__device__ __forceinline__ float2 unpack2(u64 v) {
    float2 f; asm("mov.b64 {%0, %1}, %2;" : "=f"(f.x), "=f"(f.y) : "l"(v)); return f;
}

// One accumulation stream over K:
//   acc{R,Z,a3}[ii][jp] (+)= A[b0+batch][k] * W[gate*Hn + j0+unit][k]
// BNT = units per tile (32 or 64), II = batch rows per thread (64/ (NTHREADS/(BNT/4)) ).
// Accumulators are f32x2 pairs along the unit dimension.
template<int BNT, int II>
__device__ __forceinline__ void stream_mm(
    const float* __restrict__ A, int lda, int K,
    const float* __restrict__ W, int ldw,
    int b0, int j0, int tid, bool vec,
    float (*hs)[HS_LD], float (*ws)[WS_LD],
    u64 (&aR)[II][2], u64 (&aZ)[II][2], u64 (&a3)[II][2])
{
    constexpr int WSLOTS = 3 * BNT * 4;                       // float4 slots per chunk
    constexpr int NWL = (WSLOTS + NTHREADS - 1) / NTHREADS;   // 3 (BNT=64) or 2 (BNT=32)
    const int tx = tid % (BNT / 4);
    const int ty = tid / (BNT / 4);
    const int arow = tid >> 2;    // 0..63 (batch row for staging)
    const int akv  = tid & 3;     // k-quad
    const int nch = (K + KC - 1) / KC;

    float fa[4];
    float fw[NWL][4];

    auto fetch = [&](int k0) {
        // activations
        if (vec) {
            const float4 t4 = *(const float4*)(A + (size_t)(b0 + arow) * lda + k0 + akv * 4);
            fa[0] = t4.x; fa[1] = t4.y; fa[2] = t4.z; fa[3] = t4.w;
        } else {
            #pragma unroll
            for (int i = 0; i < 4; ++i) {
                const int k = k0 + akv * 4 + i;
                fa[i] = (k < K) ? A[(size_t)(b0 + arow) * lda + k] : 0.f;
            }
        }
        // weights (rows 0..3*BNT-1 map gate-major: row = g*BNT + jr)
        #pragma unroll
        for (int s = 0; s < NWL; ++s) {
            const int slot = tid + s * NTHREADS;
            if (slot < WSLOTS) {
                const int row = slot >> 2, kv = slot & 3;
                const int g = row / BNT, jr = row % BNT;
                const float* wr = W + (size_t)(g * Hn + j0 + jr) * ldw;
                if (vec) {
                    const float4 w4 = *(const float4*)(wr + k0 + kv * 4);
                    fw[s][0] = w4.x; fw[s][1] = w4.y; fw[s][2] = w4.z; fw[s][3] = w4.w;
                } else {
                    #pragma unroll
                    for (int i = 0; i < 4; ++i) {
                        const int k = k0 + kv * 4 + i;
                        fw[s][i] = (k < K) ? wr[k] : 0.f;
                    }
                }
            }
        }
    };

    fetch(0);

    for (int c = 0; c < nch; ++c) {
        __syncthreads();   // previous user done with smem
        #pragma unroll
        for (int i = 0; i < 4; ++i) hs[akv * 4 + i][arow] = fa[i];
        #pragma unroll
        for (int s = 0; s < NWL; ++s) {
            const int slot = tid + s * NTHREADS;
            if (slot < WSLOTS) {
                const int row = slot >> 2, kv = slot & 3;
                #pragma unroll
                for (int i = 0; i < 4; ++i) ws[kv * 4 + i][row] = fw[s][i];
            }
        }
        __syncthreads();

        if (c + 1 < nch) fetch((c + 1) * KC);

        // FFMA2 core
        #pragma unroll
        for (int k = 0; k < KC; ++k) {
            u64 hd[II];
            if (II == 4) {
                const float4 hb = *(const float4*)&hs[k][ty * 4];
                hd[0] = dup2(hb.x); hd[1] = dup2(hb.y); hd[2] = dup2(hb.z); hd[3] = dup2(hb.w);
            } else {
                const float2 hb = *(const float2*)&hs[k][ty * 2];
                hd[0] = dup2(hb.x); hd[1] = dup2(hb.y);
            }
            const ulonglong2 wr = *(const ulonglong2*)&ws[k][0 * BNT + tx * 4];
            const ulonglong2 wz = *(const ulonglong2*)&ws[k][1 * BNT + tx * 4];
            const ulonglong2 wn = *(const ulonglong2*)&ws[k][2 * BNT + tx * 4];
            #pragma unroll
            for (int ii = 0; ii < II; ++ii) {
                ffma2(aR[ii][0], hd[ii], wr.x); ffma2(aR[ii][1], hd[ii], wr.y);
                ffma2(aZ[ii][0], hd[ii], wz.x); ffma2(aZ[ii][1], hd[ii], wz.y);
                ffma2(a3[ii][0], hd[ii], wn.x); ffma2(a3[ii][1], hd[ii], wn.y);
            }
        }
    }
}

template<int BNT, int II>
__device__ __forceinline__ void gru_epilogue(
    const float* __restrict__ bih, const float* __restrict__ bhh,
    const float* __restrict__ hprev, float* __restrict__ hout,
    int b0, int j0, int tid,
    u64 (&aR)[II][2], u64 (&aZ)[II][2], u64 (&aXN)[II][2], u64 (&aHN)[II][2])
{
    const int tx = tid % (BNT / 4);
    const int ty = tid / (BNT / 4);
    #pragma unroll
    for (int ii = 0; ii < II; ++ii) {
        const int b = b0 + ty * II + ii;
        #pragma unroll
        for (int jp = 0; jp < 2; ++jp) {
            const float2 r2  = unpack2(aR[ii][jp]);
            const float2 z2  = unpack2(aZ[ii][jp]);
            const float2 xn2 = unpack2(aXN[ii][jp]);
            const float2 hn2 = unpack2(aHN[ii][jp]);
            #pragma unroll
            for (int jh = 0; jh < 2; ++jh) {
                const int j = j0 + tx * 4 + jp * 2 + jh;
                const float br = bih[j] + bhh[j];
                const float bz = bih[Hn + j] + bhh[Hn + j];
                const float rv = jh ? r2.y : r2.x;
                const float zv = jh ? z2.y : z2.x;
                const float xnv = jh ? xn2.y : xn2.x;
                const float hnv = jh ? hn2.y : hn2.x;
                const float r = sigf(rv + br);
                const float z = sigf(zv + bz);
                const float n = tanhf(xnv + bih[2 * Hn + j] + r * (hnv + bhh[2 * Hn + j]));
                const float hp = hprev[(size_t)b * Hn + j];
                hout[(size_t)b * Hn + j] = (1.f - z) * n + z * hp;
            }
        }
    }
}

// Pipelined super-step l: CTAs [0,128) run layer0 at t=l (64x64 tiles),
// CTAs [128,384) run layer1 at t=l-1 (64x32 tiles) -> near-equal work per CTA.
__global__ void __launch_bounds__(NTHREADS, 2)
gru_step_kernel(const float* __restrict__ x,
                const float* __restrict__ Wih0, const float* __restrict__ Whh0,
                const float* __restrict__ bih0, const float* __restrict__ bhh0,
                const float* __restrict__ Wih1, const float* __restrict__ Whh1,
                const float* __restrict__ bih1, const float* __restrict__ bhh1,
                int l)
{
    __shared__ float hs[KC][HS_LD];
    __shared__ float ws[KC][WS_LD];

    const int cta = blockIdx.x;
    const bool L1 = (cta >= 128);
    const int t = L1 ? (l - 1) : l;
    if (t < 0 || t >= Tn) return;
    const int tid = threadIdx.x;

    if (!L1) {
        const int b0 = (cta >> 2) * 64;
        const int j0 = (cta & 3) * 64;
        u64 aR[4][2] = {}, aZ[4][2] = {}, aXN[4][2] = {}, aHN[4][2] = {};
        const float* xin   = x + (size_t)t * Bn * In0;
        const float* hprev = g_h1[(t + 1) & 1];
        float*       hout  = g_h1[t & 1];
        stream_mm<64, 4>(xin, In0, In0, Wih0, In0, b0, j0, tid, false, hs, ws, aR, aZ, aXN);
        stream_mm<64, 4>(hprev, Hn, Hn, Whh0, Hn, b0, j0, tid, true, hs, ws, aR, aZ, aHN);
        gru_epilogue<64, 4>(bih0, bhh0, hprev, hout, b0, j0, tid, aR, aZ, aXN, aHN);
    } else {
        const int idx = cta - 128;           // 0..255
        const int b0 = (idx >> 3) * 64;      // 32 batch tiles
        const int j0 = (idx & 7) * 32;       // 8 unit tiles
        u64 aR[2][2] = {}, aZ[2][2] = {}, aXN[2][2] = {}, aHN[2][2] = {};
        const float* xin   = g_h1[t & 1];    // h1[t], produced by previous launch
        const float* hprev = g_h2[(t + 1) & 1];
        float*       hout  = g_h2[t & 1];
        stream_mm<32, 2>(xin, Hn, Hn, Wih1, Hn, b0, j0, tid, true, hs, ws, aR, aZ, aXN);
        stream_mm<32, 2>(hprev, Hn, Hn, Whh1, Hn, b0, j0, tid, true, hs, ws, aR, aZ, aHN);
        gru_epilogue<32, 2>(bih1, bhh1, hprev, hout, b0, j0, tid, aR, aZ, aXN, aHN);
    }
}

// Final FC + sigmoid*2-1 on h2[T-1]. One warp per batch row.
__global__ void fc_kernel(const float* __restrict__ fcw, const float* __restrict__ fcb,
                          float* __restrict__ out)
{
    const int warp = (blockIdx.x * blockDim.x + threadIdx.x) >> 5;
    const int lane = threadIdx.x & 31;
    if (warp >= Bn) return;
    const float* h = g_h2[(Tn - 1) & 1] + (size_t)warp * Hn;
    float a0 = 0.f, a1 = 0.f, a2 = 0.f, a3 = 0.f;
    for (int k = lane; k < Hn; k += 32) {
        const float hv = h[k];
        a0 = fmaf(hv, fcw[k], a0);
        a1 = fmaf(hv, fcw[Hn + k], a1);
        a2 = fmaf(hv, fcw[2 * Hn + k], a2);
        a3 = fmaf(hv, fcw[3 * Hn + k], a3);
    }
    #pragma unroll
    for (int s = 16; s; s >>= 1) {
        a0 += __shfl_xor_sync(0xFFFFFFFFu, a0, s);
        a1 += __shfl_xor_sync(0xFFFFFFFFu, a1, s);
        a2 += __shfl_xor_sync(0xFFFFFFFFu, a2, s);
        a3 += __shfl_xor_sync(0xFFFFFFFFu, a3, s);
    }
    if (lane == 0) {
        out[warp * 4 + 0] = 2.f * sigf(a0 + fcb[0]) - 1.f;
        out[warp * 4 + 1] = 2.f * sigf(a1 + fcb[1]) - 1.f;
        out[warp * 4 + 2] = 2.f * sigf(a2 + fcb[2]) - 1.f;
        out[warp * 4 + 3] = 2.f * sigf(a3 + fcb[3]) - 1.f;
    }
}

extern "C" void kernel_launch(void* const* d_in, const int* in_sizes, int n_in,
                              void* d_out, int out_size)
{
    const float* x    = (const float*)d_in[0];
    const float* Wih0 = (const float*)d_in[1];
    const float* Whh0 = (const float*)d_in[2];
    const float* bih0 = (const float*)d_in[3];
    const float* bhh0 = (const float*)d_in[4];
    const float* Wih1 = (const float*)d_in[5];
    const float* Whh1 = (const float*)d_in[6];
    const float* bih1 = (const float*)d_in[7];
    const float* bhh1 = (const float*)d_in[8];
    const float* fcw  = (const float*)d_in[9];
    const float* fcb  = (const float*)d_in[10];
    float* out = (float*)d_out;
    (void)in_sizes; (void)n_in; (void)out_size;

    // zero the "previous state" slots used at t=0 (slot (0+1)&1 == 1)
    void *p1 = nullptr, *p2 = nullptr;
    cudaGetSymbolAddress(&p1, g_h1);
    cudaGetSymbolAddress(&p2, g_h2);
    cudaMemsetAsync((char*)p1 + sizeof(float) * (size_t)Bn * Hn, 0,
                    sizeof(float) * (size_t)Bn * Hn, 0);
    cudaMemsetAsync((char*)p2 + sizeof(float) * (size_t)Bn * Hn, 0,
                    sizeof(float) * (size_t)Bn * Hn, 0);

    for (int l = 0; l <= Tn; ++l) {
        gru_step_kernel<<<384, NTHREADS>>>(x, Wih0, Whh0, bih0, bhh0,
                                           Wih1, Whh1, bih1, bhh1, l);
    }

    fc_kernel<<<(Bn * 32) / 256, 256>>>(fcw, fcb, out);
}